// round 5
// baseline (speedup 1.0000x reference)
#include <cuda_runtime.h>

#define NGROUPS 4
#define COUNT   96
#define BATCH   8
#define IMG     224
#define NPIX    (IMG * IMG)
#define ACC_N   (NGROUPS * BATCH * COUNT)

#define KMAX    9
#define WROW    12   // padded dx stride (floats), 16B-aligned rows

// Persistent accumulators: [group][batch][channel]
__device__ float g_cnt[ACC_N];
__device__ float g_sum[ACC_N];
__device__ int   g_max[ACC_N];   // float bits; post-ReLU values >= 0 so int cmp == float cmp

// Padded, aligned weights: [group][oc][ci][dy][WROW]
__device__ float g_wpad[NGROUPS * COUNT * 3 * KMAX * WROW];

__global__ void zero_acc_kernel() {
    int i = blockIdx.x * blockDim.x + threadIdx.x;
    if (i < ACC_N) { g_cnt[i] = 0.0f; g_sum[i] = 0.0f; g_max[i] = 0; }
}

__global__ void pack_weights_kernel(const float* __restrict__ w3,
                                    const float* __restrict__ w5,
                                    const float* __restrict__ w7,
                                    const float* __restrict__ w9)
{
    int i = blockIdx.x * blockDim.x + threadIdx.x;          // over [g][oc][ci][dy][WROW]
    const int TOT = NGROUPS * COUNT * 3 * KMAX * WROW;
    if (i >= TOT) return;
    int dx = i % WROW;
    int t  = i / WROW;
    int dy = t % KMAX;  t /= KMAX;
    int ci = t % 3;     t /= 3;
    int oc = t % COUNT;
    int g  = t / COUNT;
    const int ks[4] = {3, 5, 7, 9};
    int K = ks[g];
    float v = 0.0f;
    if (dx < K && dy < K) {
        const float* W = (g == 0) ? w3 : (g == 1) ? w5 : (g == 2) ? w7 : w9;
        v = W[((oc * 3 + ci) * K + dy) * K + dx];
    }
    g_wpad[i] = v;
}

// Tile: 32x32 outputs, 64 threads. ty=tid/2 (32 rows), xb=(tid%2)*16 -> 16 px/thread.
// SWP=68 (mod 32 == 4): each 8-lane LDS.128 phase tiles all 32 banks -> conflict-free.
template <int K>
__global__ __launch_bounds__(64)
void conv_pool_kernel(const float* __restrict__ X,
                      const float* __restrict__ Bv,
                      int group)
{
    constexpr int P   = (K - 1) / 2;
    constexpr int TX  = 32;
    constexpr int TY  = 32;
    constexpr int SW  = TX + K - 1;      // <= 40
    constexpr int SH  = TY + K - 1;      // <= 40
    constexpr int SWP = 68;              // mod 32 == 4 (bank rotate), mod 4 == 0 (16B align)
    constexpr int NWV = (K + 3) / 4;     // float4s per weight row

    __shared__ float s_in[3 * SH * SWP];

    const int bx  = blockIdx.x;          // 0..6
    const int by  = blockIdx.y;          // 0..6
    const int bz  = blockIdx.z;          // batch*3 + channel-block
    const int b   = bz / 3;
    const int cb  = bz % 3;              // 32 output channels per block
    const int gx0 = bx * TX;
    const int gy0 = by * TY;
    const int tid = threadIdx.x;

    // Cooperative halo load (zero padding outside image).
    const float* Xb = X + (size_t)b * 3 * NPIX;
    for (int idx = tid; idx < 3 * SH * SW; idx += 64) {
        int ci = idx / (SH * SW);
        int r  = idx % (SH * SW);
        int sy = r / SW;
        int sx = r % SW;
        int iy = gy0 - P + sy;
        int ix = gx0 - P + sx;
        float v = 0.0f;
        if (iy >= 0 && iy < IMG && ix >= 0 && ix < IMG)
            v = Xb[(ci * IMG + iy) * IMG + ix];
        s_in[(ci * SH + sy) * SWP + sx] = v;
    }
    __syncthreads();

    const int ty = tid / 2;              // 0..31
    const int xb = (tid % 2) * 16;       // 0 or 16 (16B-aligned base)

    const int acc_base = (group * BATCH + b) * COUNT;
    const float* Wp = g_wpad + (size_t)(group * COUNT) * 3 * KMAX * WROW;

    for (int cpair = 0; cpair < 16; ++cpair) {
        const int oca = cb * 32 + cpair * 2;
        const int ocb = oca + 1;

        float accA[16], accB[16];
        #pragma unroll
        for (int j = 0; j < 16; ++j) { accA[j] = 0.0f; accB[j] = 0.0f; }

        #pragma unroll
        for (int ci = 0; ci < 3; ++ci) {
            #pragma unroll
            for (int dy = 0; dy < K; ++dy) {
                // ---- window: 6x LDS.128 (24 floats; K+15 used), conflict-free ----
                const float4* rp4 = (const float4*)&s_in[(ci * SH + ty + dy) * SWP + xb];
                float4 w4[6];
                #pragma unroll
                for (int q = 0; q < 6; ++q) w4[q] = rp4[q];
                const float* win = (const float*)w4;

                // ---- weights: NWV x LDG.128 per channel (uniform, aligned) ----
                const float4* wra = (const float4*)&Wp[((oca * 3 + ci) * KMAX + dy) * WROW];
                const float4* wrb = (const float4*)&Wp[((ocb * 3 + ci) * KMAX + dy) * WROW];
                float4 qa[NWV], qb[NWV];
                #pragma unroll
                for (int q = 0; q < NWV; ++q) { qa[q] = wra[q]; qb[q] = wrb[q]; }
                const float* wA = (const float*)qa;
                const float* wB = (const float*)qb;

                #pragma unroll
                for (int dx = 0; dx < K; ++dx) {
                    #pragma unroll
                    for (int j = 0; j < 16; ++j) {
                        accA[j] = fmaf(wA[dx], win[dx + j], accA[j]);
                        accB[j] = fmaf(wB[dx], win[dx + j], accB[j]);
                    }
                }
            }
        }

        const float biasA = __ldg(Bv + oca);
        const float biasB = __ldg(Bv + ocb);

        // ---- channel A: branchless bias + relu + stats + warp reduce ----
        {
            float cnt = 0.0f, sum = 0.0f, mx = 0.0f;
            #pragma unroll
            for (int j = 0; j < 16; ++j) {
                float v = accA[j] + biasA;
                float r = fmaxf(v, 0.0f);
                cnt += (v > 0.0f) ? 1.0f : 0.0f;
                sum += r;
                mx   = fmaxf(mx, r);
            }
            #pragma unroll
            for (int off = 16; off > 0; off >>= 1) {
                cnt += __shfl_down_sync(0xffffffffu, cnt, off);
                sum += __shfl_down_sync(0xffffffffu, sum, off);
                mx  = fmaxf(mx, __shfl_down_sync(0xffffffffu, mx, off));
            }
            if ((tid & 31) == 0) {
                int idx = acc_base + oca;
                atomicAdd(&g_cnt[idx], cnt);
                atomicAdd(&g_sum[idx], sum);
                atomicMax(&g_max[idx], __float_as_int(mx));
            }
        }
        // ---- channel B ----
        {
            float cnt = 0.0f, sum = 0.0f, mx = 0.0f;
            #pragma unroll
            for (int j = 0; j < 16; ++j) {
                float v = accB[j] + biasB;
                float r = fmaxf(v, 0.0f);
                cnt += (v > 0.0f) ? 1.0f : 0.0f;
                sum += r;
                mx   = fmaxf(mx, r);
            }
            #pragma unroll
            for (int off = 16; off > 0; off >>= 1) {
                cnt += __shfl_down_sync(0xffffffffu, cnt, off);
                sum += __shfl_down_sync(0xffffffffu, sum, off);
                mx  = fmaxf(mx, __shfl_down_sync(0xffffffffu, mx, off));
            }
            if ((tid & 31) == 0) {
                int idx = acc_base + ocb;
                atomicAdd(&g_cnt[idx], cnt);
                atomicAdd(&g_sum[idx], sum);
                atomicMax(&g_max[idx], __float_as_int(mx));
            }
        }
    }
}

__global__ void finalize_kernel(float* __restrict__ out) {
    int i = blockIdx.x * blockDim.x + threadIdx.x;
    if (i >= ACC_N) return;
    int g = i / (BATCH * COUNT);
    int r = i % (BATCH * COUNT);
    int b = r / COUNT;
    int c = r % COUNT;

    float cnt = g_cnt[i];
    float sum = g_sum[i];
    float mx  = __int_as_float(g_max[i]);

    float ppv = cnt * (1.0f / (float)NPIX);
    float mpv = (cnt > 0.0f) ? (sum / cnt) : 0.0f;

    float* o = out + (size_t)b * (NGROUPS * 3 * COUNT) + g * (3 * COUNT);
    o[c]             = ppv;
    o[COUNT + c]     = mpv;
    o[2 * COUNT + c] = mx;
}

extern "C" void kernel_launch(void* const* d_in, const int* in_sizes, int n_in,
                              void* d_out, int out_size)
{
    const float* X  = (const float*)d_in[0];
    const float* w3 = (const float*)d_in[1];
    const float* b3 = (const float*)d_in[2];
    const float* w5 = (const float*)d_in[3];
    const float* b5 = (const float*)d_in[4];
    const float* w7 = (const float*)d_in[5];
    const float* b7 = (const float*)d_in[6];
    const float* w9 = (const float*)d_in[7];
    const float* b9 = (const float*)d_in[8];
    float* out = (float*)d_out;

    zero_acc_kernel<<<(ACC_N + 255) / 256, 256>>>();

    const int WTOT = NGROUPS * COUNT * 3 * KMAX * WROW;
    pack_weights_kernel<<<(WTOT + 255) / 256, 256>>>(w3, w5, w7, w9);

    dim3 grid(7, 7, BATCH * 3);   // 7x7 tiles of 32x32, batch * channel-blocks
    conv_pool_kernel<3><<<grid, 64>>>(X, b3, 0);
    conv_pool_kernel<5><<<grid, 64>>>(X, b5, 1);
    conv_pool_kernel<7><<<grid, 64>>>(X, b7, 2);
    conv_pool_kernel<9><<<grid, 64>>>(X, b9, 3);

    finalize_kernel<<<(ACC_N + 255) / 256, 256>>>(out);
}

// round 6
// speedup vs baseline: 1.0737x; 1.0737x over previous
#include <cuda_runtime.h>

#define NGROUPS 4
#define COUNT   96
#define BATCH   8
#define IMG     224
#define NPIX    (IMG * IMG)
#define ACC_N   (NGROUPS * BATCH * COUNT)

#define KMAX    9
#define WROW    12   // padded dx stride (floats), 16B-aligned rows

// Persistent accumulators: [group][batch][channel]
__device__ float g_cnt[ACC_N];
__device__ float g_sum[ACC_N];
__device__ int   g_max[ACC_N];   // float bits; post-ReLU values >= 0 so int cmp == float cmp

// Padded, aligned weights: [group][oc][ci][dy][WROW]
__device__ float g_wpad[NGROUPS * COUNT * 3 * KMAX * WROW];

__global__ void zero_acc_kernel() {
    int i = blockIdx.x * blockDim.x + threadIdx.x;
    if (i < ACC_N) { g_cnt[i] = 0.0f; g_sum[i] = 0.0f; g_max[i] = 0; }
}

__global__ void pack_weights_kernel(const float* __restrict__ w3,
                                    const float* __restrict__ w5,
                                    const float* __restrict__ w7,
                                    const float* __restrict__ w9)
{
    int i = blockIdx.x * blockDim.x + threadIdx.x;          // over [g][oc][ci][dy][WROW]
    const int TOT = NGROUPS * COUNT * 3 * KMAX * WROW;
    if (i >= TOT) return;
    int dx = i % WROW;
    int t  = i / WROW;
    int dy = t % KMAX;  t /= KMAX;
    int ci = t % 3;     t /= 3;
    int oc = t % COUNT;
    int g  = t / COUNT;
    const int ks[4] = {3, 5, 7, 9};
    int K = ks[g];
    float v = 0.0f;
    if (dx < K && dy < K) {
        const float* W = (g == 0) ? w3 : (g == 1) ? w5 : (g == 2) ? w7 : w9;
        v = W[((oc * 3 + ci) * K + dy) * K + dx];
    }
    g_wpad[i] = v;
}

// Tile: 32x32 outputs, 128 threads (ty=tid/4, xb=(tid%4)*8).
// SWP=68 (mod 32 == 4): each 8-lane LDS.128 phase tiles all 32 banks -> conflict-free.
// 4 output channels per iteration; weights loaded in float4 chunks (16 regs reused).
template <int K>
__global__ __launch_bounds__(128)
void conv_pool_kernel(const float* __restrict__ X,
                      const float* __restrict__ Bv,
                      int group)
{
    constexpr int P    = (K - 1) / 2;
    constexpr int TX   = 32;
    constexpr int TY   = 32;
    constexpr int SW   = TX + K - 1;     // <= 40
    constexpr int SH   = TY + K - 1;     // <= 40
    constexpr int SWP  = 68;             // mod 32 == 4 (bank rotate), mod 4 == 0 (16B align)
    constexpr int NWV  = (K + 3) / 4;    // float4 chunks per weight row
    constexpr int NWIN = (K + 7 + 3) / 4;// float4s of window actually needed

    __shared__ float s_in[3 * SH * SWP];

    const int bx  = blockIdx.x;          // 0..6
    const int by  = blockIdx.y;          // 0..6
    const int bz  = blockIdx.z;          // batch*3 + channel-block
    const int b   = bz / 3;
    const int cb  = bz % 3;              // 32 output channels per block
    const int gx0 = bx * TX;
    const int gy0 = by * TY;
    const int tid = threadIdx.x;

    // Cooperative halo load (zero padding outside image).
    const float* Xb = X + (size_t)b * 3 * NPIX;
    for (int idx = tid; idx < 3 * SH * SW; idx += 128) {
        int ci = idx / (SH * SW);
        int r  = idx % (SH * SW);
        int sy = r / SW;
        int sx = r % SW;
        int iy = gy0 - P + sy;
        int ix = gx0 - P + sx;
        float v = 0.0f;
        if (iy >= 0 && iy < IMG && ix >= 0 && ix < IMG)
            v = Xb[(ci * IMG + iy) * IMG + ix];
        s_in[(ci * SH + sy) * SWP + sx] = v;
    }
    __syncthreads();

    const int ty = tid / 4;              // 0..31
    const int xb = (tid % 4) * 8;        // 0,8,16,24

    const int acc_base = (group * BATCH + b) * COUNT;
    const float* Wp = g_wpad + (size_t)(group * COUNT) * 3 * KMAX * WROW;
    constexpr int CH_STRIDE = 3 * KMAX * WROW;   // floats between consecutive oc

    for (int cq = 0; cq < 8; ++cq) {
        const int oc0 = cb * 32 + cq * 4;

        float acc[4][8];
        #pragma unroll
        for (int c = 0; c < 4; ++c)
            #pragma unroll
            for (int j = 0; j < 8; ++j) acc[c][j] = 0.0f;

        #pragma unroll
        for (int ci = 0; ci < 3; ++ci) {
            #pragma unroll
            for (int dy = 0; dy < K; ++dy) {
                // ---- window: NWIN x LDS.128, conflict-free ----
                const float4* rp4 = (const float4*)&s_in[(ci * SH + ty + dy) * SWP + xb];
                float4 w4[NWIN];
                #pragma unroll
                for (int q = 0; q < NWIN; ++q) w4[q] = rp4[q];
                const float* win = (const float*)w4;

                const float* wr0 = &Wp[((oc0 * 3 + ci) * KMAX + dy) * WROW];

                #pragma unroll
                for (int q = 0; q < NWV; ++q) {
                    // 4 channels' weight quads (16 regs, reused across 128 FMAs)
                    float4 q0 = *(const float4*)(wr0 + q * 4);
                    float4 q1 = *(const float4*)(wr0 + CH_STRIDE + q * 4);
                    float4 q2 = *(const float4*)(wr0 + 2 * CH_STRIDE + q * 4);
                    float4 q3 = *(const float4*)(wr0 + 3 * CH_STRIDE + q * 4);
                    const float* f0 = (const float*)&q0;
                    const float* f1 = (const float*)&q1;
                    const float* f2 = (const float*)&q2;
                    const float* f3 = (const float*)&q3;

                    #pragma unroll
                    for (int d = 0; d < 4; ++d) {
                        const int dx = q * 4 + d;
                        if (dx < K) {
                            #pragma unroll
                            for (int j = 0; j < 8; ++j) {
                                acc[0][j] = fmaf(f0[d], win[dx + j], acc[0][j]);
                                acc[1][j] = fmaf(f1[d], win[dx + j], acc[1][j]);
                                acc[2][j] = fmaf(f2[d], win[dx + j], acc[2][j]);
                                acc[3][j] = fmaf(f3[d], win[dx + j], acc[3][j]);
                            }
                        }
                    }
                }
            }
        }

        #pragma unroll
        for (int c = 0; c < 4; ++c) {
            const int oc = oc0 + c;
            const float bias = __ldg(Bv + oc);
            float cnt = 0.0f, sum = 0.0f, mx = 0.0f;
            #pragma unroll
            for (int j = 0; j < 8; ++j) {
                float v = acc[c][j] + bias;
                float r = fmaxf(v, 0.0f);
                cnt += (v > 0.0f) ? 1.0f : 0.0f;
                sum += r;
                mx   = fmaxf(mx, r);
            }
            #pragma unroll
            for (int off = 16; off > 0; off >>= 1) {
                cnt += __shfl_down_sync(0xffffffffu, cnt, off);
                sum += __shfl_down_sync(0xffffffffu, sum, off);
                mx  = fmaxf(mx, __shfl_down_sync(0xffffffffu, mx, off));
            }
            if ((tid & 31) == 0) {
                int idx = acc_base + oc;
                atomicAdd(&g_cnt[idx], cnt);
                atomicAdd(&g_sum[idx], sum);
                atomicMax(&g_max[idx], __float_as_int(mx));
            }
        }
    }
}

__global__ void finalize_kernel(float* __restrict__ out) {
    int i = blockIdx.x * blockDim.x + threadIdx.x;
    if (i >= ACC_N) return;
    int g = i / (BATCH * COUNT);
    int r = i % (BATCH * COUNT);
    int b = r / COUNT;
    int c = r % COUNT;

    float cnt = g_cnt[i];
    float sum = g_sum[i];
    float mx  = __int_as_float(g_max[i]);

    float ppv = cnt * (1.0f / (float)NPIX);
    float mpv = (cnt > 0.0f) ? (sum / cnt) : 0.0f;

    float* o = out + (size_t)b * (NGROUPS * 3 * COUNT) + g * (3 * COUNT);
    o[c]             = ppv;
    o[COUNT + c]     = mpv;
    o[2 * COUNT + c] = mx;
}

extern "C" void kernel_launch(void* const* d_in, const int* in_sizes, int n_in,
                              void* d_out, int out_size)
{
    const float* X  = (const float*)d_in[0];
    const float* w3 = (const float*)d_in[1];
    const float* b3 = (const float*)d_in[2];
    const float* w5 = (const float*)d_in[3];
    const float* b5 = (const float*)d_in[4];
    const float* w7 = (const float*)d_in[5];
    const float* b7 = (const float*)d_in[6];
    const float* w9 = (const float*)d_in[7];
    const float* b9 = (const float*)d_in[8];
    float* out = (float*)d_out;

    zero_acc_kernel<<<(ACC_N + 255) / 256, 256>>>();

    const int WTOT = NGROUPS * COUNT * 3 * KMAX * WROW;
    pack_weights_kernel<<<(WTOT + 255) / 256, 256>>>(w3, w5, w7, w9);

    dim3 grid(7, 7, BATCH * 3);   // 7x7 tiles of 32x32, batch * channel-blocks
    conv_pool_kernel<3><<<grid, 128>>>(X, b3, 0);
    conv_pool_kernel<5><<<grid, 128>>>(X, b5, 1);
    conv_pool_kernel<7><<<grid, 128>>>(X, b7, 2);
    conv_pool_kernel<9><<<grid, 128>>>(X, b9, 3);

    finalize_kernel<<<(ACC_N + 255) / 256, 256>>>(out);
}

// round 8
// speedup vs baseline: 1.2057x; 1.1230x over previous
#include <cuda_runtime.h>

#define NGROUPS 4
#define COUNT   96
#define BATCH   8
#define IMG     224
#define NPIX    (IMG * IMG)
#define ACC_N   (NGROUPS * BATCH * COUNT)

#define KMAX    9
#define WROW    12   // padded dx stride (floats), 16B-aligned rows

typedef unsigned long long ull;

// Persistent accumulators: [group][batch][channel]
__device__ float g_cnt[ACC_N];
__device__ float g_sum[ACC_N];
__device__ int   g_max[ACC_N];   // float bits; post-ReLU values >= 0 so int cmp == float cmp

// Padded, aligned weights: [group][oc][ci][dy][WROW]
__device__ float g_wpad[NGROUPS * COUNT * 3 * KMAX * WROW];

__global__ void zero_acc_kernel() {
    int i = blockIdx.x * blockDim.x + threadIdx.x;
    if (i < ACC_N) { g_cnt[i] = 0.0f; g_sum[i] = 0.0f; g_max[i] = 0; }
}

__global__ void pack_weights_kernel(const float* __restrict__ w3,
                                    const float* __restrict__ w5,
                                    const float* __restrict__ w7,
                                    const float* __restrict__ w9)
{
    int i = blockIdx.x * blockDim.x + threadIdx.x;          // over [g][oc][ci][dy][WROW]
    const int TOT = NGROUPS * COUNT * 3 * KMAX * WROW;
    if (i >= TOT) return;
    int dx = i % WROW;
    int t  = i / WROW;
    int dy = t % KMAX;  t /= KMAX;
    int ci = t % 3;     t /= 3;
    int oc = t % COUNT;
    int g  = t / COUNT;
    const int ks[4] = {3, 5, 7, 9};
    int K = ks[g];
    float v = 0.0f;
    if (dx < K && dy < K) {
        const float* W = (g == 0) ? w3 : (g == 1) ? w5 : (g == 2) ? w7 : w9;
        v = W[((oc * 3 + ci) * K + dy) * K + dx];
    }
    g_wpad[i] = v;
}

__device__ __forceinline__ ull pack2(float lo, float hi) {
    ull r;
    asm("mov.b64 %0, {%1, %2};" : "=l"(r) : "f"(lo), "f"(hi));
    return r;
}
__device__ __forceinline__ ull dup2(float v) {
    ull r;
    asm("mov.b64 %0, {%1, %1};" : "=l"(r) : "f"(v));
    return r;
}
__device__ __forceinline__ void fma2(ull& acc, ull a, ull b) {
#if defined(__CUDA_ARCH__) && (__CUDA_ARCH__ >= 1000)
    asm("fma.rn.f32x2 %0, %1, %2, %0;" : "+l"(acc) : "l"(a), "l"(b));
#else
    float2 A = *(float2*)&a, B = *(float2*)&b, C = *(float2*)&acc;
    C.x = fmaf(A.x, B.x, C.x);
    C.y = fmaf(A.y, B.y, C.y);
    acc = *(ull*)&C;
#endif
}

// Tile: 32x32 outputs, 128 threads (ty=tid/4, xb=(tid%4)*8).
// SWP=68 (mod 32 == 4): conflict-free LDS.128.
// 2 output channels; 8 pixels held as 4 f32x2 pairs, math via fma.rn.f32x2.
template <int K>
__global__ __launch_bounds__(128)
void conv_pool_kernel(const float* __restrict__ X,
                      const float* __restrict__ Bv,
                      int group)
{
    constexpr int P   = (K - 1) / 2;
    constexpr int TX  = 32;
    constexpr int TY  = 32;
    constexpr int SW  = TX + K - 1;      // <= 40
    constexpr int SH  = TY + K - 1;      // <= 40
    constexpr int SWP = 68;              // mod 32 == 4 (bank rotate), mod 4 == 0 (16B align)
    constexpr int NWV = (K + 3) / 4;     // float4s per weight row

    __shared__ float s_in[3 * SH * SWP];

    const int bx  = blockIdx.x;          // 0..6
    const int by  = blockIdx.y;          // 0..6
    const int bz  = blockIdx.z;          // batch*3 + channel-block
    const int b   = bz / 3;
    const int cb  = bz % 3;              // 32 output channels per block
    const int gx0 = bx * TX;
    const int gy0 = by * TY;
    const int tid = threadIdx.x;

    // Cooperative halo load (zero padding outside image).
    const float* Xb = X + (size_t)b * 3 * NPIX;
    for (int idx = tid; idx < 3 * SH * SW; idx += 128) {
        int ci = idx / (SH * SW);
        int r  = idx % (SH * SW);
        int sy = r / SW;
        int sx = r % SW;
        int iy = gy0 - P + sy;
        int ix = gx0 - P + sx;
        float v = 0.0f;
        if (iy >= 0 && iy < IMG && ix >= 0 && ix < IMG)
            v = Xb[(ci * IMG + iy) * IMG + ix];
        s_in[(ci * SH + sy) * SWP + sx] = v;
    }
    __syncthreads();

    const int ty = tid / 4;              // 0..31
    const int xb = (tid % 4) * 8;        // 0,8,16,24

    const int acc_base = (group * BATCH + b) * COUNT;
    const float* Wp = g_wpad + (size_t)(group * COUNT) * 3 * KMAX * WROW;

    for (int cpair = 0; cpair < 16; ++cpair) {
        const int oca = cb * 32 + cpair * 2;
        const int ocb = oca + 1;

        ull accA[4], accB[4];
        #pragma unroll
        for (int j = 0; j < 4; ++j) { accA[j] = 0ull; accB[j] = 0ull; }

        #pragma unroll
        for (int ci = 0; ci < 3; ++ci) {
            #pragma unroll
            for (int dy = 0; dy < K; ++dy) {
                // ---- window: 4x LDS.128 (16 floats), conflict-free ----
                const float4* rp4 = (const float4*)&s_in[(ci * SH + ty + dy) * SWP + xb];
                float4 w4[4];
                #pragma unroll
                for (int q = 0; q < 4; ++q) w4[q] = rp4[q];
                const float* w  = (const float*)w4;
                const ull*   ep = (const ull*)w4;     // even pairs (w[2i], w[2i+1]) — free

                // odd pairs (w[2i+1], w[2i+2]) — 7 packs, reused across channels & taps
                ull op[7];
                #pragma unroll
                for (int i = 0; i < 7; ++i) op[i] = pack2(w[2 * i + 1], w[2 * i + 2]);

                // ---- weights: NWV x LDG.128 per channel ----
                const float4* wra = (const float4*)&Wp[((oca * 3 + ci) * KMAX + dy) * WROW];
                const float4* wrb = (const float4*)&Wp[((ocb * 3 + ci) * KMAX + dy) * WROW];
                float4 qa[NWV], qb[NWV];
                #pragma unroll
                for (int q = 0; q < NWV; ++q) { qa[q] = wra[q]; qb[q] = wrb[q]; }
                const float* wA = (const float*)qa;
                const float* wB = (const float*)qb;

                #pragma unroll
                for (int dx = 0; dx < K; ++dx) {
                    const ull wa2 = dup2(wA[dx]);
                    const ull wb2 = dup2(wB[dx]);
                    if ((dx & 1) == 0) {
                        const int base = dx >> 1;
                        #pragma unroll
                        for (int i = 0; i < 4; ++i) {
                            fma2(accA[i], ep[base + i], wa2);
                            fma2(accB[i], ep[base + i], wb2);
                        }
                    } else {
                        const int base = (dx - 1) >> 1;
                        #pragma unroll
                        for (int i = 0; i < 4; ++i) {
                            fma2(accA[i], op[base + i], wa2);
                            fma2(accB[i], op[base + i], wb2);
                        }
                    }
                }
            }
        }

        const float biasA = __ldg(Bv + oca);
        const float biasB = __ldg(Bv + ocb);
        const float* pa = (const float*)accA;
        const float* pb = (const float*)accB;

        // ---- channel A: branchless bias + relu + stats + warp reduce ----
        {
            float cnt = 0.0f, sum = 0.0f, mx = 0.0f;
            #pragma unroll
            for (int j = 0; j < 8; ++j) {
                float v = pa[j] + biasA;
                float r = fmaxf(v, 0.0f);
                cnt += (v > 0.0f) ? 1.0f : 0.0f;
                sum += r;
                mx   = fmaxf(mx, r);
            }
            #pragma unroll
            for (int off = 16; off > 0; off >>= 1) {
                cnt += __shfl_down_sync(0xffffffffu, cnt, off);
                sum += __shfl_down_sync(0xffffffffu, sum, off);
                mx  = fmaxf(mx, __shfl_down_sync(0xffffffffu, mx, off));
            }
            if ((tid & 31) == 0) {
                int idx = acc_base + oca;
                atomicAdd(&g_cnt[idx], cnt);
                atomicAdd(&g_sum[idx], sum);
                atomicMax(&g_max[idx], __float_as_int(mx));
            }
        }
        // ---- channel B ----
        {
            float cnt = 0.0f, sum = 0.0f, mx = 0.0f;
            #pragma unroll
            for (int j = 0; j < 8; ++j) {
                float v = pb[j] + biasB;
                float r = fmaxf(v, 0.0f);
                cnt += (v > 0.0f) ? 1.0f : 0.0f;
                sum += r;
                mx   = fmaxf(mx, r);
            }
            #pragma unroll
            for (int off = 16; off > 0; off >>= 1) {
                cnt += __shfl_down_sync(0xffffffffu, cnt, off);
                sum += __shfl_down_sync(0xffffffffu, sum, off);
                mx  = fmaxf(mx, __shfl_down_sync(0xffffffffu, mx, off));
            }
            if ((tid & 31) == 0) {
                int idx = acc_base + ocb;
                atomicAdd(&g_cnt[idx], cnt);
                atomicAdd(&g_sum[idx], sum);
                atomicMax(&g_max[idx], __float_as_int(mx));
            }
        }
    }
}

__global__ void finalize_kernel(float* __restrict__ out) {
    int i = blockIdx.x * blockDim.x + threadIdx.x;
    if (i >= ACC_N) return;
    int g = i / (BATCH * COUNT);
    int r = i % (BATCH * COUNT);
    int b = r / COUNT;
    int c = r % COUNT;

    float cnt = g_cnt[i];
    float sum = g_sum[i];
    float mx  = __int_as_float(g_max[i]);

    float ppv = cnt * (1.0f / (float)NPIX);
    float mpv = (cnt > 0.0f) ? (sum / cnt) : 0.0f;

    float* o = out + (size_t)b * (NGROUPS * 3 * COUNT) + g * (3 * COUNT);
    o[c]             = ppv;
    o[COUNT + c]     = mpv;
    o[2 * COUNT + c] = mx;
}

extern "C" void kernel_launch(void* const* d_in, const int* in_sizes, int n_in,
                              void* d_out, int out_size)
{
    const float* X  = (const float*)d_in[0];
    const float* w3 = (const float*)d_in[1];
    const float* b3 = (const float*)d_in[2];
    const float* w5 = (const float*)d_in[3];
    const float* b5 = (const float*)d_in[4];
    const float* w7 = (const float*)d_in[5];
    const float* b7 = (const float*)d_in[6];
    const float* w9 = (const float*)d_in[7];
    const float* b9 = (const float*)d_in[8];
    float* out = (float*)d_out;

    zero_acc_kernel<<<(ACC_N + 255) / 256, 256>>>();

    const int WTOT = NGROUPS * COUNT * 3 * KMAX * WROW;
    pack_weights_kernel<<<(WTOT + 255) / 256, 256>>>(w3, w5, w7, w9);

    dim3 grid(7, 7, BATCH * 3);   // 7x7 tiles of 32x32, batch * channel-blocks
    conv_pool_kernel<3><<<grid, 128>>>(X, b3, 0);
    conv_pool_kernel<5><<<grid, 128>>>(X, b5, 1);
    conv_pool_kernel<7><<<grid, 128>>>(X, b7, 2);
    conv_pool_kernel<9><<<grid, 128>>>(X, b9, 3);

    finalize_kernel<<<(ACC_N + 255) / 256, 256>>>(out);
}

// round 10
// speedup vs baseline: 1.5346x; 1.2728x over previous
#include <cuda_runtime.h>
#include <cuda_bf16.h>

#define NGROUPS 4
#define COUNT   96
#define BATCH   8
#define IMG     224
#define NPIX    (IMG * IMG)
#define ACC_N   (NGROUPS * BATCH * COUNT)
#define KSMAX   16
#define NCH     56      // pixels per CTA chunk (7 n-tiles of 8)
#define LW      64      // staged raw row width

typedef unsigned int u32;

__device__ float g_cnt[ACC_N];
__device__ float g_sum[ACC_N];
__device__ int   g_max[ACC_N];
// A fragments prepacked in m16n8k16 register layout: [g][term][mtile][ks][lane][4] u32
__device__ u32 g_afrag[NGROUPS * 2 * 6 * KSMAX * 128];

__global__ void zero_acc_kernel() {
    int i = blockIdx.x * blockDim.x + threadIdx.x;
    if (i < ACC_N) { g_cnt[i] = 0.0f; g_sum[i] = 0.0f; g_max[i] = 0; }
}

__device__ __forceinline__ unsigned short bf16_bits(float v) {
    __nv_bfloat16 b = __float2bfloat16(v);
    return __bfloat16_as_ushort(b);
}

__global__ void prepack_afrag_kernel(const float* __restrict__ w3, const float* __restrict__ w5,
                                     const float* __restrict__ w7, const float* __restrict__ w9)
{
    int i = blockIdx.x * blockDim.x + threadIdx.x;
    const int TOT = NGROUPS * 2 * 6 * KSMAX * 128;
    if (i >= TOT) return;
    int r  = i & 3;
    int l  = (i >> 2) & 31;
    int ks = (i >> 7) & 15;
    int hi = i >> 11;              // [g][t][mt]
    int mt = hi % 6;
    int t  = (hi / 6) % 2;
    int g  = hi / 12;
    const int kss[4] = {3, 5, 7, 9};
    int K = kss[g], KK = K * K, K3 = 3 * KK;
    const float* W = (g == 0) ? w3 : (g == 1) ? w5 : (g == 2) ? w7 : w9;

    int row = (l >> 2) + (r & 1) * 8;
    int oc  = mt * 16 + row;                       // < 96 always
    int kb  = ks * 16 + (l & 3) * 2 + ((r >> 1) & 1) * 8;

    unsigned short us[2];
    #pragma unroll
    for (int e = 0; e < 2; ++e) {
        int k = kb + e;
        float v = 0.0f;
        if (k < K3) {
            int ci = k / KK, rem = k - ci * KK;
            int dy = rem / K, dx = rem - dy * K;
            v = W[((oc * 3 + ci) * K + dy) * K + dx];
        }
        float h = __bfloat162float(__float2bfloat16(v));
        us[e] = (t == 0) ? bf16_bits(v) : bf16_bits(v - h);
    }
    g_afrag[i] = (u32)us[0] | ((u32)us[1] << 16);
}

__device__ __forceinline__ u32 smem_u32(const void* p) {
    u32 a;
    asm("{ .reg .u64 t; cvta.to.shared.u64 t, %1; cvt.u32.u64 %0, t; }" : "=r"(a) : "l"(p));
    return a;
}

__device__ __forceinline__ void mma16816(float* c, const u32* a, u32 b0, u32 b1) {
    asm volatile(
        "mma.sync.aligned.m16n8k16.row.col.f32.bf16.bf16.f32 "
        "{%0,%1,%2,%3}, {%4,%5,%6,%7}, {%8,%9}, {%0,%1,%2,%3};"
        : "+f"(c[0]), "+f"(c[1]), "+f"(c[2]), "+f"(c[3])
        : "r"(a[0]), "r"(a[1]), "r"(a[2]), "r"(a[3]), "r"(b0), "r"(b1));
}
__device__ __forceinline__ void ldsm_x2(u32& b0, u32& b1, u32 addr) {
    asm volatile("ldmatrix.sync.aligned.m8n8.x2.shared.b16 {%0,%1}, [%2];"
                 : "=r"(b0), "=r"(b1) : "r"(addr));
}

// CTA = (nchunk, y, batch). 192 threads, 6 warps (one m16 oc-tile each).
template <int K>
__global__ __launch_bounds__(192)
void conv_mma_kernel(const float* __restrict__ X, const float* __restrict__ Bv, int group)
{
    constexpr int P = (K - 1) / 2, KK = K * K, K3 = 3 * KK;
    constexpr int KS = (K3 + 15) / 16;
    constexpr int KPAD = KS * 16 + 8;      // odd 16B-stride -> conflict-free ldmatrix

    __shared__ __nv_bfloat16 rawH[3 * K * LW];
    __shared__ __nv_bfloat16 rawL[3 * K * LW];
    __shared__ __align__(16) __nv_bfloat16 Bt[NCH * KPAD];

    const int n0   = blockIdx.x * NCH;
    const int y    = blockIdx.y;
    const int b    = blockIdx.z;
    const int tid  = threadIdx.x;
    const int w    = tid >> 5;
    const int lane = tid & 31;

    // ---- stage raw rows (bf16 hi/lo), zero outside image ----
    const float* Xb = X + (size_t)b * 3 * NPIX;
    for (int i = tid; i < 3 * K * LW; i += 192) {
        int ci = i / (K * LW);
        int r  = i % (K * LW);
        int dy = r / LW, j = r % LW;
        int iy = y - P + dy, ix = n0 - P + j;
        float v = 0.0f;
        if (iy >= 0 && iy < IMG && ix >= 0 && ix < IMG)
            v = Xb[(ci * IMG + iy) * IMG + ix];
        __nv_bfloat16 h = __float2bfloat16(v);
        rawH[i] = h;
        rawL[i] = __float2bfloat16(v - __bfloat162float(h));
    }
    __syncthreads();

    float acc[7][4];
    #pragma unroll
    for (int nt = 0; nt < 7; ++nt)
        #pragma unroll
        for (int c = 0; c < 4; ++c) acc[nt][c] = 0.0f;

    const u32* afH = &g_afrag[(((group * 2 + 0) * 6 + w) * KSMAX) * 128];
    const u32* afL = &g_afrag[(((group * 2 + 1) * 6 + w) * KSMAX) * 128];

    const u32 btBase = smem_u32(Bt);
    const u32 lmOff  = (u32)((((lane & 7) * KPAD) + ((lane >> 3) & 1) * 8) * 2);

    // ================= pass 0: B = hi slab; terms AhBh + AlBh =================
    for (int i = tid; i < NCH * KS * 16; i += 192) {
        int n = i / (KS * 16), k = i % (KS * 16);
        __nv_bfloat16 v = __float2bfloat16(0.0f);
        if (k < K3) {
            int ci = k / KK, rem = k - ci * KK;
            int dy = rem / K, dx = rem - dy * K;
            v = rawH[(ci * K + dy) * LW + n + dx];
        }
        Bt[n * KPAD + k] = v;
    }
    __syncthreads();

    #pragma unroll 1
    for (int ks = 0; ks < KS; ++ks) {
        u32 ah[4], al[4];
        #pragma unroll
        for (int r = 0; r < 4; ++r) {
            ah[r] = afH[ks * 128 + lane * 4 + r];
            al[r] = afL[ks * 128 + lane * 4 + r];
        }
        #pragma unroll
        for (int nt = 0; nt < 7; ++nt) {
            u32 b0, b1;
            ldsm_x2(b0, b1, btBase + lmOff + (u32)((nt * 8 * KPAD + ks * 16) * 2));
            mma16816(acc[nt], ah, b0, b1);
            mma16816(acc[nt], al, b0, b1);
        }
    }
    __syncthreads();

    // ================= pass 1: B = lo slab; term AhBl =================
    for (int i = tid; i < NCH * KS * 16; i += 192) {
        int n = i / (KS * 16), k = i % (KS * 16);
        __nv_bfloat16 v = __float2bfloat16(0.0f);
        if (k < K3) {
            int ci = k / KK, rem = k - ci * KK;
            int dy = rem / K, dx = rem - dy * K;
            v = rawL[(ci * K + dy) * LW + n + dx];
        }
        Bt[n * KPAD + k] = v;
    }
    __syncthreads();

    #pragma unroll 1
    for (int ks = 0; ks < KS; ++ks) {
        u32 ah[4];
        #pragma unroll
        for (int r = 0; r < 4; ++r) ah[r] = afH[ks * 128 + lane * 4 + r];
        #pragma unroll
        for (int nt = 0; nt < 7; ++nt) {
            u32 b0, b1;
            ldsm_x2(b0, b1, btBase + lmOff + (u32)((nt * 8 * KPAD + ks * 16) * 2));
            mma16816(acc[nt], ah, b0, b1);
        }
    }

    // ================= epilogue: bias+relu+pool, quad reduce, atomics =================
    const int ocbase = w * 16;
    const int r0 = lane >> 2;
    const float bias0 = Bv[ocbase + r0];
    const float bias1 = Bv[ocbase + r0 + 8];
    float cnt0 = 0, sum0 = 0, mx0 = 0, cnt1 = 0, sum1 = 0, mx1 = 0;
    #pragma unroll
    for (int nt = 0; nt < 7; ++nt) {
        #pragma unroll
        for (int c = 0; c < 2; ++c) {
            float v = acc[nt][c] + bias0;
            float rl = fmaxf(v, 0.0f);
            cnt0 += (v > 0.0f) ? 1.0f : 0.0f; sum0 += rl; mx0 = fmaxf(mx0, rl);
        }
        #pragma unroll
        for (int c = 2; c < 4; ++c) {
            float v = acc[nt][c] + bias1;
            float rl = fmaxf(v, 0.0f);
            cnt1 += (v > 0.0f) ? 1.0f : 0.0f; sum1 += rl; mx1 = fmaxf(mx1, rl);
        }
    }
    #pragma unroll
    for (int m = 1; m <= 2; m <<= 1) {
        cnt0 += __shfl_xor_sync(0xffffffffu, cnt0, m);
        sum0 += __shfl_xor_sync(0xffffffffu, sum0, m);
        mx0   = fmaxf(mx0, __shfl_xor_sync(0xffffffffu, mx0, m));
        cnt1 += __shfl_xor_sync(0xffffffffu, cnt1, m);
        sum1 += __shfl_xor_sync(0xffffffffu, sum1, m);
        mx1   = fmaxf(mx1, __shfl_xor_sync(0xffffffffu, mx1, m));
    }
    if ((lane & 3) == 0) {
        int base = (group * BATCH + b) * COUNT + ocbase;
        int i0 = base + r0, i1 = base + r0 + 8;
        atomicAdd(&g_cnt[i0], cnt0); atomicAdd(&g_sum[i0], sum0);
        atomicMax(&g_max[i0], __float_as_int(mx0));
        atomicAdd(&g_cnt[i1], cnt1); atomicAdd(&g_sum[i1], sum1);
        atomicMax(&g_max[i1], __float_as_int(mx1));
    }
}

__global__ void finalize_kernel(float* __restrict__ out) {
    int i = blockIdx.x * blockDim.x + threadIdx.x;
    if (i >= ACC_N) return;
    int g = i / (BATCH * COUNT);
    int r = i % (BATCH * COUNT);
    int b = r / COUNT;
    int c = r % COUNT;
    float cnt = g_cnt[i];
    float sum = g_sum[i];
    float mx  = __int_as_float(g_max[i]);
    float ppv = cnt * (1.0f / (float)NPIX);
    float mpv = (cnt > 0.0f) ? (sum / cnt) : 0.0f;
    float* o = out + (size_t)b * (NGROUPS * 3 * COUNT) + g * (3 * COUNT);
    o[c]             = ppv;
    o[COUNT + c]     = mpv;
    o[2 * COUNT + c] = mx;
}

extern "C" void kernel_launch(void* const* d_in, const int* in_sizes, int n_in,
                              void* d_out, int out_size)
{
    const float* X  = (const float*)d_in[0];
    const float* w3 = (const float*)d_in[1];
    const float* b3 = (const float*)d_in[2];
    const float* w5 = (const float*)d_in[3];
    const float* b5 = (const float*)d_in[4];
    const float* w7 = (const float*)d_in[5];
    const float* b7 = (const float*)d_in[6];
    const float* w9 = (const float*)d_in[7];
    const float* b9 = (const float*)d_in[8];
    float* out = (float*)d_out;

    zero_acc_kernel<<<(ACC_N + 255) / 256, 256>>>();
    const int TOT = NGROUPS * 2 * 6 * KSMAX * 128;
    prepack_afrag_kernel<<<(TOT + 255) / 256, 256>>>(w3, w5, w7, w9);

    dim3 grid(IMG / NCH, IMG, BATCH);   // (4 chunks, 224 rows, 8 batches)
    conv_mma_kernel<3><<<grid, 192>>>(X, b3, 0);
    conv_mma_kernel<5><<<grid, 192>>>(X, b5, 1);
    conv_mma_kernel<7><<<grid, 192>>>(X, b7, 2);
    conv_mma_kernel<9><<<grid, 192>>>(X, b9, 3);

    finalize_kernel<<<(ACC_N + 255) / 256, 256>>>(out);
}

// round 11
// speedup vs baseline: 1.9323x; 1.2591x over previous
#include <cuda_runtime.h>
#include <cuda_bf16.h>

#define NGROUPS 4
#define COUNT   96
#define BATCH   8
#define IMG     224
#define NPIX    (IMG * IMG)
#define ACC_N   (NGROUPS * BATCH * COUNT)
#define KSMAX   16
#define NCH     56      // pixels per CTA chunk (7 n-tiles of 8)
#define LW      64      // staged raw row width

typedef unsigned int u32;

__device__ float g_cnt[ACC_N];
__device__ float g_sum[ACC_N];
__device__ int   g_max[ACC_N];
// A fragments prepacked in m16n8k16 register layout: [g][term][mtile][ks][lane][4] u32
__device__ u32 g_afrag[NGROUPS * 2 * 6 * KSMAX * 128];

__global__ void zero_acc_kernel() {
    int i = blockIdx.x * blockDim.x + threadIdx.x;
    if (i < ACC_N) { g_cnt[i] = 0.0f; g_sum[i] = 0.0f; g_max[i] = 0; }
}

__device__ __forceinline__ unsigned short bf16_bits(float v) {
    __nv_bfloat16 b = __float2bfloat16(v);
    return __bfloat16_as_ushort(b);
}

__global__ void prepack_afrag_kernel(const float* __restrict__ w3, const float* __restrict__ w5,
                                     const float* __restrict__ w7, const float* __restrict__ w9)
{
    int i = blockIdx.x * blockDim.x + threadIdx.x;
    const int TOT = NGROUPS * 2 * 6 * KSMAX * 128;
    if (i >= TOT) return;
    int r  = i & 3;
    int l  = (i >> 2) & 31;
    int ks = (i >> 7) & 15;
    int hi = i >> 11;              // [g][t][mt]
    int mt = hi % 6;
    int t  = (hi / 6) % 2;
    int g  = hi / 12;
    const int kss[4] = {3, 5, 7, 9};
    int K = kss[g], KK = K * K, K3 = 3 * KK;
    const float* W = (g == 0) ? w3 : (g == 1) ? w5 : (g == 2) ? w7 : w9;

    int row = (l >> 2) + (r & 1) * 8;
    int oc  = mt * 16 + row;
    int kb  = ks * 16 + (l & 3) * 2 + ((r >> 1) & 1) * 8;

    unsigned short us[2];
    #pragma unroll
    for (int e = 0; e < 2; ++e) {
        int k = kb + e;
        float v = 0.0f;
        if (k < K3) {
            int ci = k / KK, rem = k - ci * KK;
            int dy = rem / K, dx = rem - dy * K;
            v = W[((oc * 3 + ci) * K + dy) * K + dx];
        }
        float h = __bfloat162float(__float2bfloat16(v));
        us[e] = (t == 0) ? bf16_bits(v) : bf16_bits(v - h);
    }
    g_afrag[i] = (u32)us[0] | ((u32)us[1] << 16);
}

__device__ __forceinline__ u32 smem_u32(const void* p) {
    u32 a;
    asm("{ .reg .u64 t; cvta.to.shared.u64 t, %1; cvt.u32.u64 %0, t; }" : "=r"(a) : "l"(p));
    return a;
}
__device__ __forceinline__ void mma16816(float* c, const u32* a, u32 b0, u32 b1) {
    asm volatile(
        "mma.sync.aligned.m16n8k16.row.col.f32.bf16.bf16.f32 "
        "{%0,%1,%2,%3}, {%4,%5,%6,%7}, {%8,%9}, {%0,%1,%2,%3};"
        : "+f"(c[0]), "+f"(c[1]), "+f"(c[2]), "+f"(c[3])
        : "r"(a[0]), "r"(a[1]), "r"(a[2]), "r"(a[3]), "r"(b0), "r"(b1));
}
__device__ __forceinline__ void ldsm_x2(u32& b0, u32& b1, u32 addr) {
    asm volatile("ldmatrix.sync.aligned.m8n8.x2.shared.b16 {%0,%1}, [%2];"
                 : "=r"(b0), "=r"(b1) : "r"(addr));
}

// smem sizing helpers (host+device)
__host__ __device__ constexpr int ks_of(int K)    { return (3 * K * K + 15) / 16; }
__host__ __device__ constexpr int ks16_of(int K)  { return ks_of(K) * 16; }
__host__ __device__ constexpr int kpad_of(int K)  { return ks16_of(K) + 8; }   // odd 16B-stride
__host__ __device__ constexpr int slab_bytes(int K) { return NCH * kpad_of(K) * 2; }
__host__ __device__ constexpr int dyn_bytes(int K)  { return 2 * slab_bytes(K); }

// CTA = (nchunk, y, batch). 192 threads, 6 warps (one m16 oc-tile each).
template <int K>
__global__ __launch_bounds__(192)
void conv_mma_kernel(const float* __restrict__ X, const float* __restrict__ Bv, int group)
{
    constexpr int P = (K - 1) / 2, KK = K * K, K3 = 3 * KK;
    constexpr int KS = ks_of(K);
    constexpr int KS16 = ks16_of(K);
    constexpr int KPAD = kpad_of(K);

    __shared__ __nv_bfloat16 rawH[3 * K * LW];
    __shared__ __nv_bfloat16 rawL[3 * K * LW];
    __shared__ int s_ofs[KS16];
    extern __shared__ __align__(16) char dynsm[];
    __nv_bfloat16* BtH = (__nv_bfloat16*)dynsm;
    __nv_bfloat16* BtL = (__nv_bfloat16*)(dynsm + slab_bytes(K));

    const int n0   = blockIdx.x * NCH;
    const int y    = blockIdx.y;
    const int b    = blockIdx.z;
    const int tid  = threadIdx.x;
    const int w    = tid >> 5;
    const int lane = tid & 31;

    // ---- k -> raw-offset table (one entry per padded k) ----
    for (int k = tid; k < KS16; k += 192) {
        int o = -1;
        if (k < K3) {
            int ci = k / KK, rem = k - ci * KK;
            int dy = rem / K, dx = rem - dy * K;
            o = (ci * K + dy) * LW + dx;
        }
        s_ofs[k] = o;
    }

    // ---- stage raw rows (bf16 hi/lo), zero outside image ----
    const float* Xb = X + (size_t)b * 3 * NPIX;
    for (int i = tid; i < 3 * K * LW; i += 192) {
        int ci = i / (K * LW);
        int r  = i % (K * LW);
        int dy = r / LW, j = r % LW;
        int iy = y - P + dy, ix = n0 - P + j;
        float v = 0.0f;
        if (iy >= 0 && iy < IMG && ix >= 0 && ix < IMG)
            v = Xb[(ci * IMG + iy) * IMG + ix];
        __nv_bfloat16 h = __float2bfloat16(v);
        rawH[i] = h;
        rawL[i] = __float2bfloat16(v - __bfloat162float(h));
    }
    __syncthreads();

    // ---- build BOTH B slabs in one pass (table-driven, no div/mod) ----
    const __nv_bfloat16 z = __float2bfloat16(0.0f);
    for (int i = tid; i < NCH * KS16; i += 192) {
        int n = i / KS16, k = i - n * KS16;     // div by compile-time const
        int o = s_ofs[k];
        __nv_bfloat16 h = z, l = z;
        if (o >= 0) { h = rawH[o + n]; l = rawL[o + n]; }
        int d = n * KPAD + k;
        BtH[d] = h;
        BtL[d] = l;
    }
    __syncthreads();

    float acc[7][4];
    #pragma unroll
    for (int nt = 0; nt < 7; ++nt)
        #pragma unroll
        for (int c = 0; c < 4; ++c) acc[nt][c] = 0.0f;

    const u32* afH = &g_afrag[(((group * 2 + 0) * 6 + w) * KSMAX) * 128];
    const u32* afL = &g_afrag[(((group * 2 + 1) * 6 + w) * KSMAX) * 128];

    const u32 lmRow = (u32)((((lane & 7) * KPAD) + ((lane >> 3) & 1) * 8) * 2);
    const u32 bhBase = smem_u32(BtH) + lmRow;
    const u32 blBase = smem_u32(BtL) + lmRow;

    // ---- merged mainloop: 3 split terms per ks ----
    #pragma unroll
    for (int ks = 0; ks < KS; ++ks) {
        u32 ah[4], al[4];
        #pragma unroll
        for (int r = 0; r < 4; ++r) {
            ah[r] = afH[ks * 128 + lane * 4 + r];
            al[r] = afL[ks * 128 + lane * 4 + r];
        }
        #pragma unroll
        for (int nt = 0; nt < 7; ++nt) {
            const u32 off = (u32)((nt * 8 * KPAD + ks * 16) * 2);
            u32 b0, b1;
            ldsm_x2(b0, b1, bhBase + off);
            mma16816(acc[nt], ah, b0, b1);
            mma16816(acc[nt], al, b0, b1);
            u32 c0, c1;
            ldsm_x2(c0, c1, blBase + off);
            mma16816(acc[nt], ah, c0, c1);
        }
    }

    // ---- epilogue: bias+relu+pool, quad reduce, atomics ----
    const int ocbase = w * 16;
    const int r0 = lane >> 2;
    const float bias0 = Bv[ocbase + r0];
    const float bias1 = Bv[ocbase + r0 + 8];
    float cnt0 = 0, sum0 = 0, mx0 = 0, cnt1 = 0, sum1 = 0, mx1 = 0;
    #pragma unroll
    for (int nt = 0; nt < 7; ++nt) {
        #pragma unroll
        for (int c = 0; c < 2; ++c) {
            float v = acc[nt][c] + bias0;
            float rl = fmaxf(v, 0.0f);
            cnt0 += (v > 0.0f) ? 1.0f : 0.0f; sum0 += rl; mx0 = fmaxf(mx0, rl);
        }
        #pragma unroll
        for (int c = 2; c < 4; ++c) {
            float v = acc[nt][c] + bias1;
            float rl = fmaxf(v, 0.0f);
            cnt1 += (v > 0.0f) ? 1.0f : 0.0f; sum1 += rl; mx1 = fmaxf(mx1, rl);
        }
    }
    #pragma unroll
    for (int m = 1; m <= 2; m <<= 1) {
        cnt0 += __shfl_xor_sync(0xffffffffu, cnt0, m);
        sum0 += __shfl_xor_sync(0xffffffffu, sum0, m);
        mx0   = fmaxf(mx0, __shfl_xor_sync(0xffffffffu, mx0, m));
        cnt1 += __shfl_xor_sync(0xffffffffu, cnt1, m);
        sum1 += __shfl_xor_sync(0xffffffffu, sum1, m);
        mx1   = fmaxf(mx1, __shfl_xor_sync(0xffffffffu, mx1, m));
    }
    if ((lane & 3) == 0) {
        int base = (group * BATCH + b) * COUNT + ocbase;
        int i0 = base + r0, i1 = base + r0 + 8;
        atomicAdd(&g_cnt[i0], cnt0); atomicAdd(&g_sum[i0], sum0);
        atomicMax(&g_max[i0], __float_as_int(mx0));
        atomicAdd(&g_cnt[i1], cnt1); atomicAdd(&g_sum[i1], sum1);
        atomicMax(&g_max[i1], __float_as_int(mx1));
    }
}

__global__ void finalize_kernel(float* __restrict__ out) {
    int i = blockIdx.x * blockDim.x + threadIdx.x;
    if (i >= ACC_N) return;
    int g = i / (BATCH * COUNT);
    int r = i % (BATCH * COUNT);
    int b = r / COUNT;
    int c = r % COUNT;
    float cnt = g_cnt[i];
    float sum = g_sum[i];
    float mx  = __int_as_float(g_max[i]);
    float ppv = cnt * (1.0f / (float)NPIX);
    float mpv = (cnt > 0.0f) ? (sum / cnt) : 0.0f;
    float* o = out + (size_t)b * (NGROUPS * 3 * COUNT) + g * (3 * COUNT);
    o[c]             = ppv;
    o[COUNT + c]     = mpv;
    o[2 * COUNT + c] = mx;
}

extern "C" void kernel_launch(void* const* d_in, const int* in_sizes, int n_in,
                              void* d_out, int out_size)
{
    const float* X  = (const float*)d_in[0];
    const float* w3 = (const float*)d_in[1];
    const float* b3 = (const float*)d_in[2];
    const float* w5 = (const float*)d_in[3];
    const float* b5 = (const float*)d_in[4];
    const float* w7 = (const float*)d_in[5];
    const float* b7 = (const float*)d_in[6];
    const float* w9 = (const float*)d_in[7];
    const float* b9 = (const float*)d_in[8];
    float* out = (float*)d_out;

    cudaFuncSetAttribute(conv_mma_kernel<3>, cudaFuncAttributeMaxDynamicSharedMemorySize, dyn_bytes(3));
    cudaFuncSetAttribute(conv_mma_kernel<5>, cudaFuncAttributeMaxDynamicSharedMemorySize, dyn_bytes(5));
    cudaFuncSetAttribute(conv_mma_kernel<7>, cudaFuncAttributeMaxDynamicSharedMemorySize, dyn_bytes(7));
    cudaFuncSetAttribute(conv_mma_kernel<9>, cudaFuncAttributeMaxDynamicSharedMemorySize, dyn_bytes(9));

    zero_acc_kernel<<<(ACC_N + 255) / 256, 256>>>();
    const int TOT = NGROUPS * 2 * 6 * KSMAX * 128;
    prepack_afrag_kernel<<<(TOT + 255) / 256, 256>>>(w3, w5, w7, w9);

    dim3 grid(IMG / NCH, IMG, BATCH);   // (4 chunks, 224 rows, 8 batches)
    conv_mma_kernel<3><<<grid, 192, dyn_bytes(3)>>>(X, b3, 0);
    conv_mma_kernel<5><<<grid, 192, dyn_bytes(5)>>>(X, b5, 1);
    conv_mma_kernel<7><<<grid, 192, dyn_bytes(7)>>>(X, b7, 2);
    conv_mma_kernel<9><<<grid, 192, dyn_bytes(9)>>>(X, b9, 3);

    finalize_kernel<<<(ACC_N + 255) / 256, 256>>>(out);
}